// round 15
// baseline (speedup 1.0000x reference)
#include <cuda_runtime.h>
#include <cuda_fp16.h>
#include <cstdint>

// LightGCN: 3 layers of SpMM + running-mean accumulator.
// N=400000 nodes, D=64, E=4000000 edges.
// out = (x0 + x1 + x2 + x3) / 4, x_{k+1} = A @ x_k (A sparse COO, fp32 vals)
//
// CSR build once, emb pre-converted to fp16, then three warp-per-row
// atomic-free fp16-gather SpMM layers. Warp lanes = 4 edge slots x 8 dim
// slots -> no intra-warp degree divergence; shfl-reduce over edge slots.
// Final layer fuses out = 0.25*(emb_fp32 + x1 + x2 + x3).

#define NUM_NODES 400000
#define EMB_DIM   64
#define NELEM     (NUM_NODES * EMB_DIM)   // 25,600,000
#define MAX_EDGES 4000000
#define SCAN_BLK  512
#define NB_SCAN   ((NUM_NODES + SCAN_BLK - 1) / SCAN_BLK)   // 782

// fp16 buffers (51.2 MB each): h0 = emb_fp16, h1/h2 ping-pong
__device__ __half g_h0[NELEM];
__device__ __half g_h1[NELEM];
__device__ __half g_h2[NELEM];

// CSR scratch
__device__ int  g_cnt[NUM_NODES];
__device__ int  g_rowptr[NUM_NODES];
__device__ int  g_ofs[NUM_NODES];
__device__ int  g_part[1024];
__device__ int2 g_edge[MAX_EDGES];     // {col, val_bits}
__device__ int  g_is64;

// ---------------------------------------------------------------------------
// dtype detect: int64 indices have all-zero high words (indices < 400000).
// ---------------------------------------------------------------------------
__global__ void detect_kernel(const unsigned int* __restrict__ raw) {
    __shared__ unsigned int s;
    if (threadIdx.x == 0) s = 0u;
    __syncthreads();
    unsigned int acc = 0u;
    for (int i = threadIdx.x; i < 1024; i += blockDim.x)
        acc |= raw[2 * i + 1];
    atomicOr(&s, acc);
    __syncthreads();
    if (threadIdx.x == 0) g_is64 = (s == 0u) ? 1 : 0;
}

__global__ void zero_cnt_kernel() {
    int i = blockIdx.x * blockDim.x + threadIdx.x;
    if (i < NUM_NODES) g_cnt[i] = 0;
}

__global__ void hist_kernel(const unsigned int* __restrict__ row_raw,
                            int n_edges) {
    int e = blockIdx.x * blockDim.x + threadIdx.x;
    if (e >= n_edges) return;
    int idx = g_is64 ? (2 * e) : e;
    atomicAdd(&g_cnt[(int)row_raw[idx]], 1);
}

// ---------------------------------------------------------------------------
// two-level exclusive scan of g_cnt -> g_rowptr (and g_ofs copy)
// ---------------------------------------------------------------------------
__global__ void scanA_kernel() {
    __shared__ int sh[SCAN_BLK];
    int tid = threadIdx.x;
    int gid = blockIdx.x * SCAN_BLK + tid;
    int v = (gid < NUM_NODES) ? g_cnt[gid] : 0;
    sh[tid] = v;
    __syncthreads();
    for (int off = 1; off < SCAN_BLK; off <<= 1) {
        int t = (tid >= off) ? sh[tid - off] : 0;
        __syncthreads();
        if (tid >= off) sh[tid] += t;
        __syncthreads();
    }
    if (gid < NUM_NODES) g_rowptr[gid] = sh[tid] - v;
    if (tid == SCAN_BLK - 1) g_part[blockIdx.x] = sh[tid];
}

__global__ void scanB_kernel() {
    __shared__ int sh[1024];
    int tid = threadIdx.x;
    int v = (tid < NB_SCAN) ? g_part[tid] : 0;
    sh[tid] = v;
    __syncthreads();
    for (int off = 1; off < 1024; off <<= 1) {
        int t = (tid >= off) ? sh[tid - off] : 0;
        __syncthreads();
        if (tid >= off) sh[tid] += t;
        __syncthreads();
    }
    if (tid < NB_SCAN) g_part[tid] = sh[tid] - v;
}

__global__ void scanC_kernel() {
    int i = blockIdx.x * blockDim.x + threadIdx.x;
    if (i >= NUM_NODES) return;
    int rp = g_rowptr[i] + g_part[i / SCAN_BLK];
    g_rowptr[i] = rp;
    g_ofs[i]    = rp;
}

__global__ void scatter_kernel(const unsigned int* __restrict__ row_raw,
                               const unsigned int* __restrict__ col_raw,
                               const float* __restrict__ val,
                               int n_edges) {
    int e = blockIdx.x * blockDim.x + threadIdx.x;
    if (e >= n_edges) return;
    int idx = g_is64 ? (2 * e) : e;
    int r = (int)row_raw[idx];
    int c = (int)col_raw[idx];
    int pos = atomicAdd(&g_ofs[r], 1);
    g_edge[pos] = make_int2(c, __float_as_int(val[e]));
}

// ---------------------------------------------------------------------------
// emb fp32 -> fp16 conversion, 8 floats per thread, float4 I/O
// ---------------------------------------------------------------------------
__global__ void conv_kernel(const float4* __restrict__ src,
                            float4* __restrict__ dst) {   // dst = half buffer
    int i = blockIdx.x * blockDim.x + threadIdx.x;        // 8-float chunk idx
    if (i >= NELEM / 8) return;
    float4 a = src[2 * i];
    float4 b = src[2 * i + 1];
    float4 r;
    __half2* h = reinterpret_cast<__half2*>(&r);
    h[0] = __float22half2_rn(make_float2(a.x, a.y));
    h[1] = __float22half2_rn(make_float2(a.z, a.w));
    h[2] = __float22half2_rn(make_float2(b.x, b.y));
    h[3] = __float22half2_rn(make_float2(b.z, b.w));
    dst[i] = r;
}

// ---------------------------------------------------------------------------
// helpers
// ---------------------------------------------------------------------------
__device__ __forceinline__ float4 pack8h(const float* a) {
    float4 r;
    __half2* h = reinterpret_cast<__half2*>(&r);
    h[0] = __float22half2_rn(make_float2(a[0], a[1]));
    h[1] = __float22half2_rn(make_float2(a[2], a[3]));
    h[2] = __float22half2_rn(make_float2(a[4], a[5]));
    h[3] = __float22half2_rn(make_float2(a[6], a[7]));
    return r;
}

__device__ __forceinline__ void accum8h(float* a, float4 x, float v) {
    const __half2* h = reinterpret_cast<const __half2*>(&x);
#pragma unroll
    for (int j = 0; j < 4; j++) {
        float2 f = __half22float2(h[j]);
        a[2 * j]     = fmaf(v, f.x, a[2 * j]);
        a[2 * j + 1] = fmaf(v, f.y, a[2 * j + 1]);
    }
}

// ---------------------------------------------------------------------------
// warp-per-row fp16-gather SpMM.
// lane = e_sub (lane>>3, 4 edge slots) x dim (lane&7, 8 float4 slots).
// Each iteration consumes 4 edges warp-uniformly (no divergence); unroll x2
// keeps 2 gathers in flight per lane. Partial sums over e_sub groups are
// combined with 2 shfl_xor stages; lanes 0-7 write the 128 B row.
// mode 0: dst = acc (fp16)
// mode 1: out = 0.25*(emb_fp32 + x1 + x2 + acc)
// ---------------------------------------------------------------------------
__global__ void __launch_bounds__(256)
spmm_w_kernel(const __half* __restrict__ src,
              __half* __restrict__ dst,
              const float* __restrict__ emb,
              const __half* __restrict__ x1,
              const __half* __restrict__ x2,
              float* __restrict__ out,
              int final_mode) {
    int gwarp = (blockIdx.x * blockDim.x + threadIdx.x) >> 5;
    if (gwarp >= NUM_NODES) return;
    int r     = gwarp;
    int lane  = threadIdx.x & 31;
    int e_sub = lane >> 3;     // 0..3
    int dim   = lane & 7;      // float4 slot within row

    int start = g_rowptr[r];   // warp-uniform broadcast
    int deg   = g_cnt[r];

    float a[8];
#pragma unroll
    for (int j = 0; j < 8; j++) a[j] = 0.f;

    const float4* s4 = reinterpret_cast<const float4*>(src);  // 8 halves each

    int i = e_sub;
    for (; i + 4 < deg; i += 8) {
        int2 eA = __ldg(&g_edge[start + i]);
        int2 eB = __ldg(&g_edge[start + i + 4]);
        float4 xA = __ldg(s4 + (((size_t)eA.x) << 3) + dim);
        float4 xB = __ldg(s4 + (((size_t)eB.x) << 3) + dim);
        accum8h(a, xA, __int_as_float(eA.y));
        accum8h(a, xB, __int_as_float(eB.y));
    }
    if (i < deg) {
        int2 eA = __ldg(&g_edge[start + i]);
        float4 xA = __ldg(s4 + (((size_t)eA.x) << 3) + dim);
        accum8h(a, xA, __int_as_float(eA.y));
    }

    // reduce the 4 e_sub partial sums (butterfly over lane bits 3,4)
#pragma unroll
    for (int off = 8; off <= 16; off <<= 1) {
#pragma unroll
        for (int j = 0; j < 8; j++)
            a[j] += __shfl_xor_sync(0xffffffffu, a[j], off);
    }

    if (e_sub != 0) return;    // lanes 0-7 own the writeback

    size_t hofs = ((size_t)r << 3) + dim;        // float4 index, half buffers
    if (!final_mode) {
        reinterpret_cast<float4*>(dst)[hofs] = pack8h(a);
    } else {
        size_t fofs = ((size_t)r << 4) + (dim << 1);  // float4 index, fp32
        const float4* E = reinterpret_cast<const float4*>(emb);
        float4 e0 = __ldg(E + fofs), e1 = __ldg(E + fofs + 1);

        float u[8], w[8];
        {
            float4 xh = __ldg(reinterpret_cast<const float4*>(x1) + hofs);
            const __half2* h = reinterpret_cast<const __half2*>(&xh);
#pragma unroll
            for (int j = 0; j < 4; j++) {
                float2 f = __half22float2(h[j]);
                u[2*j] = f.x; u[2*j+1] = f.y;
            }
        }
        {
            float4 xh = __ldg(reinterpret_cast<const float4*>(x2) + hofs);
            const __half2* h = reinterpret_cast<const __half2*>(&xh);
#pragma unroll
            for (int j = 0; j < 4; j++) {
                float2 f = __half22float2(h[j]);
                w[2*j] = f.x; w[2*j+1] = f.y;
            }
        }

        float4 r0, r1;
        r0.x = 0.25f * (e0.x + u[0] + w[0] + a[0]);
        r0.y = 0.25f * (e0.y + u[1] + w[1] + a[1]);
        r0.z = 0.25f * (e0.z + u[2] + w[2] + a[2]);
        r0.w = 0.25f * (e0.w + u[3] + w[3] + a[3]);
        r1.x = 0.25f * (e1.x + u[4] + w[4] + a[4]);
        r1.y = 0.25f * (e1.y + u[5] + w[5] + a[5]);
        r1.z = 0.25f * (e1.z + u[6] + w[6] + a[6]);
        r1.w = 0.25f * (e1.w + u[7] + w[7] + a[7]);
        reinterpret_cast<float4*>(out)[fofs]     = r0;
        reinterpret_cast<float4*>(out)[fofs + 1] = r1;
    }
}

// ---------------------------------------------------------------------------
// launch
// ---------------------------------------------------------------------------
extern "C" void kernel_launch(void* const* d_in, const int* in_sizes, int n_in,
                              void* d_out, int out_size) {
    // Order-robust binding: embedding is the unique input with NELEM elements;
    // the remaining three, in original order, are row, col, val.
    int emb_idx = -1;
    for (int i = 0; i < n_in; i++)
        if (in_sizes[i] == NELEM) { emb_idx = i; break; }
    if (emb_idx < 0) emb_idx = 0;

    int others[3]; int k = 0;
    for (int i = 0; i < n_in && k < 3; i++)
        if (i != emb_idx) others[k++] = i;

    const float*        emb     = (const float*)d_in[emb_idx];
    const unsigned int* row_raw = (const unsigned int*)d_in[others[0]];
    const unsigned int* col_raw = (const unsigned int*)d_in[others[1]];
    const float*        val     = (const float*)d_in[others[2]];
    float*              out     = (float*)d_out;
    const int n_edges = in_sizes[others[0]];

    __half *h0 = nullptr, *h1 = nullptr, *h2 = nullptr;
    cudaGetSymbolAddress((void**)&h0, g_h0);
    cudaGetSymbolAddress((void**)&h1, g_h1);
    cudaGetSymbolAddress((void**)&h2, g_h2);

    const int TB = 256;
    const int grid_edges = (n_edges + TB - 1) / TB;
    const int grid_nodes = (NUM_NODES + TB - 1) / TB;
    const int grid_conv  = (NELEM / 8 + TB - 1) / TB;
    const int grid_spmm  = (NUM_NODES * 32 + TB - 1) / TB;   // warp per row

    // ---- CSR build + emb fp16 conversion ----
    detect_kernel<<<1, 256>>>(row_raw);
    zero_cnt_kernel<<<grid_nodes, TB>>>();
    hist_kernel<<<grid_edges, TB>>>(row_raw, n_edges);
    conv_kernel<<<grid_conv, TB>>>((const float4*)emb, (float4*)h0);
    scanA_kernel<<<NB_SCAN, SCAN_BLK>>>();
    scanB_kernel<<<1, 1024>>>();
    scanC_kernel<<<grid_nodes, TB>>>();
    scatter_kernel<<<grid_edges, TB>>>(row_raw, col_raw, val, n_edges);

    // ---- 3 propagation layers (warp-per-row, fp16 gathers) ----
    // layer 1: h0 -> h1
    spmm_w_kernel<<<grid_spmm, TB>>>(h0, h1, nullptr, nullptr, nullptr, nullptr, 0);
    // layer 2: h1 -> h2
    spmm_w_kernel<<<grid_spmm, TB>>>(h1, h2, nullptr, nullptr, nullptr, nullptr, 0);
    // layer 3: h2 -> out = 0.25*(emb + x1 + x2 + x3), fused
    spmm_w_kernel<<<grid_spmm, TB>>>(h2, nullptr, emb, h1, h2, out, 1);
}